// round 10
// baseline (speedup 1.0000x reference)
#include <cuda_runtime.h>
#include <cstdint>

#define Hh 512
#define Ww 512
#define Cc 32
#define Bb 4
#define Ss (Hh*Ww)
#define NG 4               // channel groups
#define CPG (Cc/NG)        // 8 channels per group

// Partial per-pixel (off_x, off_y) per channel-group: 4 * 8MB = 32 MB scratch
__device__ float2 g_off_part[NG][Bb * Ss];

typedef unsigned long long ull;

__device__ __forceinline__ ull pack2(float a, float b) {
    ull r; asm("mov.b64 %0, {%1, %2};" : "=l"(r) : "f"(a), "f"(b)); return r;
}
__device__ __forceinline__ void unpack2(ull v, float& a, float& b) {
    asm("mov.b64 {%0, %1}, %2;" : "=f"(a), "=f"(b) : "l"(v));
}
__device__ __forceinline__ ull fma2(ull a, ull b, ull c) {
    ull d; asm("fma.rn.f32x2 %0, %1, %2, %3;" : "=l"(d) : "l"(a), "l"(b), "l"(c)); return d;
}

// ---------------------------------------------------------------------------
// Kernel 1: channel-split barrier-free offset conv (R9 design, R10: runs on a
// PAIR of batches so its x-reads + partial-writes stay L2-resident for the
// immediately following sampler launch).
// Warp strip = 128px x 4 rows; per channel stream 6 rows (aligned LDG.128 +
// 2 edge scalars), rotate into 9-tap packed-f32x2 accumulation. No barriers.
// blockIdx.z encodes (local_batch, group): 8 values for a 2-batch pair.
// Partials stored with DEFAULT caching (we WANT them resident in L2).
// ---------------------------------------------------------------------------
__global__ __launch_bounds__(64) void conv_off_kernel(
    const float* __restrict__ x,
    const float* __restrict__ w_off,
    const float* __restrict__ b_off,
    int b0)
{
    __shared__ ull s_wk[CPG * 9];   // packed (w_ch0, w_ch1), this group's 8 ch

    const int tid  = threadIdx.x;
    const int wid  = tid >> 5;
    const int lane = tid & 31;

    const int grp = blockIdx.z & (NG - 1);
    const int bz  = b0 + (blockIdx.z >> 2);   // batch
    const int c0  = grp * CPG;

    for (int i = tid; i < CPG * 9; i += 64)
        s_wk[i] = pack2(__ldg(w_off + c0 * 9 + i),
                        __ldg(w_off + 288 + c0 * 9 + i));
    __syncthreads();

    const int X0   = blockIdx.x * 128;
    const int ytop = blockIdx.y * 8 + wid * 4;   // out rows ytop..ytop+3
    const int cb   = X0 + 4 * lane;              // lane's first pixel column
    const float* xb = x + (size_t)bz * Cc * Ss;

    // bias only in group 0's partial
    const ull initp = (grp == 0) ? pack2(__ldg(b_off + 0), __ldg(b_off + 1))
                                 : pack2(0.0f, 0.0f);
    ull acc[4][4];
#pragma unroll
    for (int r = 0; r < 4; r++)
#pragma unroll
        for (int p = 0; p < 4; p++) acc[r][p] = initp;

    const bool has_left  = (cb > 0);
    const bool has_right = (cb + 4 < Ww);

#pragma unroll
    for (int c = 0; c < CPG; c++) {
        const float* xc = xb + (size_t)(c0 + c) * Ss;

        ull wk[9];
#pragma unroll
        for (int k = 0; k < 9; k++) wk[k] = s_wk[c * 9 + k];

#pragma unroll
        for (int j = 0; j < 6; j++) {           // input rows ytop-1 .. ytop+4
            int gy = ytop - 1 + j;
            float v0 = 0.f, v1 = 0.f, v2 = 0.f, v3 = 0.f, v4 = 0.f, v5 = 0.f;
            if ((unsigned)gy < (unsigned)Hh) {
                const float* rp = xc + gy * Ww + cb;
                float4 m = __ldg(reinterpret_cast<const float4*>(rp));
                v1 = m.x; v2 = m.y; v3 = m.z; v4 = m.w;
                if (has_left)  v0 = __ldg(rp - 1);
                if (has_right) v5 = __ldg(rp + 4);
            }
            ull pv[6];
            pv[0] = pack2(v0, v0); pv[1] = pack2(v1, v1);
            pv[2] = pack2(v2, v2); pv[3] = pack2(v3, v3);
            pv[4] = pack2(v4, v4); pv[5] = pack2(v5, v5);

#pragma unroll
            for (int ky = 0; ky < 3; ky++) {
                int r = j - ky;
                if (r >= 0 && r < 4) {          // compile-time (j,ky unrolled)
#pragma unroll
                    for (int p = 0; p < 4; p++) {
                        ull a = acc[r][p];
                        a = fma2(pv[p],     wk[ky * 3 + 0], a);
                        a = fma2(pv[p + 1], wk[ky * 3 + 1], a);
                        a = fma2(pv[p + 2], wk[ky * 3 + 2], a);
                        acc[r][p] = a;
                    }
                }
            }
        }
    }

    // store 4 rows x 4 px of partial (off_x, off_y): two STG.128 per row.
    // DEFAULT caching: these are re-read by the sampler right after -> L2 hit.
#pragma unroll
    for (int r = 0; r < 4; r++) {
        int y = ytop + r;
        float2* op = g_off_part[grp] + (size_t)bz * Ss + (size_t)y * Ww + cb;
        float ox0, oy0, ox1, oy1, ox2, oy2, ox3, oy3;
        unpack2(acc[r][0], ox0, oy0);
        unpack2(acc[r][1], ox1, oy1);
        unpack2(acc[r][2], ox2, oy2);
        unpack2(acc[r][3], ox3, oy3);
        *reinterpret_cast<float4*>(op)     = make_float4(ox0, oy0, ox1, oy1);
        *reinterpret_cast<float4*>(op + 2) = make_float4(ox2, oy2, ox3, oy3);
    }
}

// ---------------------------------------------------------------------------
// Kernel 2: bilinear sampling (proven path), for a 2-batch pair whose x and
// partial buffers are L2-resident from the preceding conv launch. Sums the 4
// partial offsets, full clamp+validity (jnp semantics), coalesced channel
// loop, streaming out-stores (out has no reuse).
// ---------------------------------------------------------------------------
__global__ __launch_bounds__(256) void sample_kernel(
    const float* __restrict__ x,
    float* __restrict__ out,
    int b0)
{
    const int px = blockIdx.x * 64 + threadIdx.x;
    const int py = blockIdx.y * 4 + threadIdx.y;
    const int b  = b0 + blockIdx.z;

    const size_t oidx = (size_t)b * Ss + (size_t)py * Ww + px;
    float2 p0 = __ldg(&g_off_part[0][oidx]);
    float2 p1 = __ldg(&g_off_part[1][oidx]);
    float2 p2 = __ldg(&g_off_part[2][oidx]);
    float2 p3 = __ldg(&g_off_part[3][oidx]);
    float offx = (p0.x + p1.x) + (p2.x + p3.x);
    float offy = (p0.y + p1.y) + (p2.y + p3.y);

    float ix = (float)px + offx;
    float iy = (float)py + offy;

    float x0f = floorf(ix);
    float y0f = floorf(iy);
    float wx1 = ix - x0f, wx0 = 1.0f - wx1;
    float wy1 = iy - y0f, wy0 = 1.0f - wy1;

    float fx0 = (x0f >= 0.0f && x0f <= 511.0f) ? 1.0f : 0.0f;
    float fx1 = (x0f >= -1.0f && x0f <= 510.0f) ? 1.0f : 0.0f;
    float fy0 = (y0f >= 0.0f && y0f <= 511.0f) ? 1.0f : 0.0f;
    float fy1 = (y0f >= -1.0f && y0f <= 510.0f) ? 1.0f : 0.0f;

    int ix0r = (int)x0f;
    int iy0r = (int)y0f;
    int xi0 = max(0, min(511, ix0r));
    int xi1 = max(0, min(511, ix0r + 1));
    int yi0 = max(0, min(511, iy0r));
    int yi1 = max(0, min(511, iy0r + 1));

    float w00 = wy0 * wx0 * (fy0 * fx0);
    float w01 = wy0 * wx1 * (fy0 * fx1);
    float w10 = wy1 * wx0 * (fy1 * fx0);
    float w11 = wy1 * wx1 * (fy1 * fx1);

    const int i00 = yi0 * Ww + xi0;
    const int i01 = yi0 * Ww + xi1;
    const int i10 = yi1 * Ww + xi0;
    const int i11 = yi1 * Ww + xi1;

    const float* xb = x + (size_t)b * Cc * Ss;
    size_t o = (size_t)b * Cc * Ss + (size_t)py * Ww + px;

#pragma unroll 4
    for (int c = 0; c < Cc; c++) {
        const float* p = xb + (size_t)c * Ss;
        float v = w00 * __ldg(p + i00)
                + w01 * __ldg(p + i01)
                + w10 * __ldg(p + i10)
                + w11 * __ldg(p + i11);
        __stcs(out + o + (size_t)c * Ss, v);
    }
}

extern "C" void kernel_launch(void* const* d_in, const int* in_sizes, int n_in,
                              void* d_out, int out_size)
{
    const float* x     = (const float*)d_in[0];  // (4, 32, 512, 512)
    const float* w_off = (const float*)d_in[1];  // (18, 32, 3, 3)
    const float* b_off = (const float*)d_in[2];  // (18,)
    float* out = (float*)d_out;                  // (4, 32, 512, 512)

    (void)in_sizes; (void)n_in; (void)out_size;

    // Batch-paired pipeline: each conv pair's x-reads and partial-writes
    // (2*(33.5MB + 8MB) = 83MB) stay L2-resident (126MB) for the sampler
    // that immediately follows -> sampler x-reads served from L2, DRAM
    // x-traffic ~halved chip-wide.
    dim3 gc(Ww / 128, Hh / 8, 2 * NG);   // (4, 64, 8) = 2048 blocks x 64 thr
    dim3 gs(Ww / 64, Hh / 4, 2);         // (8, 128, 2) blocks x 256 thr
    dim3 ts(64, 4);

    conv_off_kernel<<<gc, 64>>>(x, w_off, b_off, 0);
    sample_kernel<<<gs, ts>>>(x, out, 0);
    conv_off_kernel<<<gc, 64>>>(x, w_off, b_off, 2);
    sample_kernel<<<gs, ts>>>(x, out, 2);
}